// round 7
// baseline (speedup 1.0000x reference)
#include <cuda_runtime.h>
#include <math.h>
#include <stdint.h>

#define TTOK 2048
#define HDIM 1024
#define ENUM 8
#define IDIM 4096
#define VDIM 32000
#define KTOP 2

// ---- static scratch (no allocation allowed) ----
__device__ float g_x[(size_t)TTOK * HDIM];
__device__ float g_h[(size_t)ENUM * TTOK * IDIM];
__device__ float g_eo[(size_t)TTOK * HDIM];
__device__ int   g_sel[TTOK * KTOP];
__device__ int   g_list[ENUM][TTOK];
__device__ int   g_cnt[ENUM];

// ======================= helpers =======================
__device__ __forceinline__ uint32_t smem_u32(const void* p) {
    uint32_t a;
    asm("{ .reg .u64 t; cvta.to.shared.u64 t, %1; cvt.u32.u64 %0, t; }" : "=r"(a) : "l"(p));
    return a;
}
__device__ __forceinline__ uint32_t lds32(uint32_t a) {
    uint32_t v;
    asm volatile("ld.shared.b32 %0, [%1];" : "=r"(v) : "r"(a));
    return v;
}
__device__ __forceinline__ uint32_t cvt_rna(uint32_t x) {
    uint32_t v;
    asm("cvt.rna.tf32.f32 %0, %1;" : "=r"(v) : "r"(x));
    return v;
}
#define CP16Z(dst, src, sz) \
    asm volatile("cp.async.cg.shared.global [%0], [%1], 16, %2;" \
                 :: "r"(dst), "l"(src), "r"(sz))
#define CPCOMMIT() asm volatile("cp.async.commit_group;")
#define CPWAIT(n)  asm volatile("cp.async.wait_group %0;" :: "n"(n))

#define MMA_TF32(d, a, b)                                                      \
    asm volatile(                                                              \
        "mma.sync.aligned.m16n8k8.row.col.f32.tf32.tf32.f32 "                  \
        "{%0,%1,%2,%3},{%4,%5,%6,%7},{%8,%9},{%0,%1,%2,%3};"                   \
        : "+f"((d)[0]), "+f"((d)[1]), "+f"((d)[2]), "+f"((d)[3])               \
        : "r"((a)[0]), "r"((a)[1]), "r"((a)[2]), "r"((a)[3]),                  \
          "r"((b)[0]), "r"((b)[1]))

// ======================= small kernels =======================
__global__ void setup_kernel(const int* __restrict__ ids,
                             const float* __restrict__ emb,
                             const float* __restrict__ rw,
                             const float* __restrict__ rb,
                             float* __restrict__ out_rw,
                             float* __restrict__ out_se) {
    int t = blockIdx.x;
    int tid = threadIdx.x;
    int row = ids[t];
    const float* src = emb + (size_t)row * HDIM;
    const float4* s4 = (const float4*)src;
    float4* d4 = (float4*)(g_x + (size_t)t * HDIM);
    for (int i = tid; i < HDIM / 4; i += blockDim.x) d4[i] = s4[i];

    float acc[ENUM];
#pragma unroll
    for (int e = 0; e < ENUM; e++) acc[e] = 0.f;
    for (int k = tid; k < HDIM; k += blockDim.x) {
        float xv = src[k];
        const float* wr = rw + (size_t)k * ENUM;
#pragma unroll
        for (int e = 0; e < ENUM; e++) acc[e] = fmaf(xv, wr[e], acc[e]);
    }
    __shared__ float sred[ENUM][128];
#pragma unroll
    for (int e = 0; e < ENUM; e++) sred[e][tid] = acc[e];
    __syncthreads();
    for (int s = 64; s > 0; s >>= 1) {
        if (tid < s) {
#pragma unroll
            for (int e = 0; e < ENUM; e++) sred[e][tid] += sred[e][tid + s];
        }
        __syncthreads();
    }
    if (tid == 0) {
        float lg[ENUM];
#pragma unroll
        for (int e = 0; e < ENUM; e++) lg[e] = sred[e][0] + rb[e];
        int i0 = 0; float v0 = lg[0];
#pragma unroll
        for (int e = 1; e < ENUM; e++) if (lg[e] > v0) { v0 = lg[e]; i0 = e; }
        int i1 = -1; float v1 = -3.0e38f;
#pragma unroll
        for (int e = 0; e < ENUM; e++) if (e != i0 && lg[e] > v1) { v1 = lg[e]; i1 = e; }
        float ee = expf(v1 - v0);
        float denom = 1.0f + ee;
        g_sel[t * 2 + 0] = i0;
        g_sel[t * 2 + 1] = i1;
        if (out_rw) { out_rw[t * 2 + 0] = 1.0f / denom; out_rw[t * 2 + 1] = ee / denom; }
        if (out_se) { out_se[t * 2 + 0] = (float)i0; out_se[t * 2 + 1] = (float)i1; }
    }
}

__global__ void build_lists_kernel() {
    int e = blockIdx.x;
    int tid = threadIdx.x;
    int lane = tid & 31, wid = tid >> 5;
    __shared__ int wtot[8];
    __shared__ int s_base;
    if (tid == 0) s_base = 0;
    __syncthreads();
    for (int base = 0; base < TTOK; base += 256) {
        int t = base + tid;
        int f = (g_sel[t * 2] == e || g_sel[t * 2 + 1] == e) ? 1 : 0;
        unsigned bal = __ballot_sync(0xffffffffu, f);
        int lpfx = __popc(bal & ((1u << lane) - 1u));
        if (lane == 0) wtot[wid] = __popc(bal);
        __syncthreads();
        int woff = 0;
        for (int w = 0; w < wid; w++) woff += wtot[w];
        if (f) g_list[e][s_base + woff + lpfx] = t;
        int tot = 0;
        for (int w = 0; w < 8; w++) tot += wtot[w];
        __syncthreads();
        if (tid == 0) s_base += tot;
        __syncthreads();
    }
    if (tid == 0) g_cnt[e] = s_base;
}

__global__ void zero_eo_kernel() {
    size_t i = (size_t)blockIdx.x * blockDim.x + threadIdx.x;
    if (i < (size_t)TTOK * HDIM / 4) {
        ((float4*)g_eo)[i] = make_float4(0.f, 0.f, 0.f, 0.f);
    }
}

// ======================= tf32 mma.sync GEMM, 128x256 CTA tile =======================
// MODE 0: FFN1  gelu(Xg[e] @ w1[e] + b1[e]) -> g_h
// MODE 1: FFN2  (H[e] @ w2[e] + b2[e]) atomic-> g_eo
// MODE 2: LM    g_eo @ lm_w + lm_b -> out
//
// CTA 128x256, 8 warps (2x4), warp tile 64x64, KC=16, double-buffered cp.async.

#define KC   16
#define SA   20      // A smem row stride (floats)
#define SBW  264     // B smem row stride (floats)
#define ABUF (128 * SA * 4)        // 10240
#define BBUF (KC * SBW * 4)        // 16896
#define BOFF (2 * ABUF)            // 20480
#define LISTOFF (BOFF + 2 * BBUF)  // 54272
#define SMEMSZ  (LISTOFF + 512)    // 54784

template <int MODE>
__global__ void __launch_bounds__(256, 1) gemm_mma(
    const float* __restrict__ Bglob,
    const float* __restrict__ bias,
    float* __restrict__ Out,
    int Ktot, int ldb)
{
    int e = blockIdx.z;
    int cnt = (MODE == 2) ? TTOK : g_cnt[e];
    int n0 = blockIdx.x * 256;
    int m0 = blockIdx.y * 128;
    if (m0 >= cnt) return;

    extern __shared__ char smem[];
    int* s_list = (int*)(smem + LISTOFF);
    uint32_t sbase = smem_u32(smem);

    int tid = threadIdx.x;
    int lane = tid & 31;
    int wid = tid >> 5;
    int wm = wid >> 2;       // 0..1 (m)
    int wn = wid & 3;        // 0..3 (n)

    const float* Bg;
    const float* be;
    if (MODE == 0)      { Bg = Bglob + (size_t)e * HDIM * IDIM; be = bias + (size_t)e * IDIM; }
    else if (MODE == 1) { Bg = Bglob + (size_t)e * IDIM * HDIM; be = bias + (size_t)e * HDIM; }
    else                { Bg = Bglob; be = bias; }

    if (MODE != 2 && tid < 128) {
        int gm = m0 + tid;
        s_list[tid] = (gm < cnt) ? g_list[e][gm] : -1;
    }
    __syncthreads();

    // ---- cp.async assignments ----
    // A: 128 rows x 4 chunks(16B); thread handles idx=tid and tid+256.
    int ar1 = tid >> 2, ar2 = ar1 + 64;
    int ac = tid & 3;
    const float* a1p; const float* a2p;
    uint32_t p1, p2;
    if (MODE == 0) {
        int t1 = s_list[ar1], t2 = s_list[ar2];
        a1p = (t1 >= 0) ? g_x + (size_t)t1 * HDIM + ac * 4 : g_x;
        a2p = (t2 >= 0) ? g_x + (size_t)t2 * HDIM + ac * 4 : g_x;
        p1 = (t1 >= 0) ? 16u : 0u;
        p2 = (t2 >= 0) ? 16u : 0u;
    } else if (MODE == 1) {
        bool v1 = (m0 + ar1) < cnt, v2 = (m0 + ar2) < cnt;
        a1p = v1 ? g_h + ((size_t)e * TTOK + m0 + ar1) * IDIM + ac * 4 : g_h;
        a2p = v2 ? g_h + ((size_t)e * TTOK + m0 + ar2) * IDIM + ac * 4 : g_h;
        p1 = v1 ? 16u : 0u;
        p2 = v2 ? 16u : 0u;
    } else {
        a1p = g_eo + (size_t)(m0 + ar1) * HDIM + ac * 4;
        a2p = g_eo + (size_t)(m0 + ar2) * HDIM + ac * 4;
        p1 = p2 = 16u;
    }
    uint32_t ad1 = sbase + (uint32_t)(ar1 * SA * 4 + ac * 16);
    uint32_t ad2 = sbase + (uint32_t)(ar2 * SA * 4 + ac * 16);

    // B: 16 rows x 64 chunks(16B); thread handles 4: kb = tid>>6 + 4*i, cbc = tid&63
    int kb0 = tid >> 6;
    int cbc = tid & 63;
    const float* bsrc = Bg + n0 + cbc * 4;
    uint32_t bd[4];
#pragma unroll
    for (int i = 0; i < 4; i++)
        bd[i] = sbase + BOFF + (uint32_t)((kb0 + 4 * i) * SBW * 4 + cbc * 16);

    float d[4][8][4];
#pragma unroll
    for (int i = 0; i < 4; i++)
#pragma unroll
        for (int j = 0; j < 8; j++)
#pragma unroll
            for (int r = 0; r < 4; r++) d[i][j][r] = 0.f;

    int nit = Ktot / KC;

    // prefetch tile 0
    CP16Z(ad1, a1p, p1);
    CP16Z(ad2, a2p, p2);
#pragma unroll
    for (int i = 0; i < 4; i++)
        CP16Z(bd[i], bsrc + (size_t)(kb0 + 4 * i) * ldb, 16u);
    CPCOMMIT();

    int arb = wm * 64 + (lane >> 2);
    int akc = lane & 3;
    int bnc = wn * 64 + (lane >> 2);

    for (int it = 0; it < nit; ++it) {
        int buf = it & 1;
        if (it + 1 < nit) {
            int nbuf = (it + 1) & 1;
            int k0 = (it + 1) * KC;
            uint32_t ao = (uint32_t)(nbuf * ABUF);
            uint32_t bo = (uint32_t)(nbuf * BBUF);
            CP16Z(ad1 + ao, a1p + k0, p1);
            CP16Z(ad2 + ao, a2p + k0, p2);
#pragma unroll
            for (int i = 0; i < 4; i++)
                CP16Z(bd[i] + bo, bsrc + (size_t)(k0 + kb0 + 4 * i) * ldb, 16u);
            CPCOMMIT();
            CPWAIT(1);
        } else {
            CPWAIT(0);
        }
        __syncthreads();

        uint32_t abase = sbase + (uint32_t)(buf * ABUF);
        uint32_t bbase = sbase + BOFF + (uint32_t)(buf * BBUF);
#pragma unroll
        for (int ks = 0; ks < 2; ks++) {
            int c0 = ks * 8 + akc;
            uint32_t a[4][4];
#pragma unroll
            for (int i = 0; i < 4; i++) {
                int r0 = arb + i * 16;
                a[i][0] = cvt_rna(lds32(abase + (uint32_t)((r0 * SA + c0) * 4)));
                a[i][1] = cvt_rna(lds32(abase + (uint32_t)(((r0 + 8) * SA + c0) * 4)));
                a[i][2] = cvt_rna(lds32(abase + (uint32_t)((r0 * SA + c0 + 4) * 4)));
                a[i][3] = cvt_rna(lds32(abase + (uint32_t)(((r0 + 8) * SA + c0 + 4) * 4)));
            }
            uint32_t b[8][2];
#pragma unroll
            for (int j = 0; j < 8; j++) {
                b[j][0] = cvt_rna(lds32(bbase + (uint32_t)((c0 * SBW + bnc + j * 8) * 4)));
                b[j][1] = cvt_rna(lds32(bbase + (uint32_t)(((c0 + 4) * SBW + bnc + j * 8) * 4)));
            }
#pragma unroll
            for (int i = 0; i < 4; i++)
#pragma unroll
                for (int j = 0; j < 8; j++) MMA_TF32(d[i][j], a[i], b[j]);
        }
        __syncthreads();
    }

    // ---- epilogue ----
    int row_l0 = wm * 64 + (lane >> 2);
    int col_l0 = wn * 64 + (lane & 3) * 2;
    float2 bj[8];
#pragma unroll
    for (int j = 0; j < 8; j++) {
        bj[j].x = be[n0 + col_l0 + j * 8];
        bj[j].y = be[n0 + col_l0 + j * 8 + 1];
    }

#pragma unroll
    for (int i = 0; i < 4; i++) {
        int rl = row_l0 + i * 16;
#pragma unroll
        for (int half = 0; half < 2; half++) {
            int r = rl + half * 8;
            int m = m0 + r;
            if (MODE != 2 && m >= cnt) continue;
#pragma unroll
            for (int j = 0; j < 8; j++) {
                int cl = col_l0 + j * 8;
                float v0 = d[i][j][half * 2 + 0] + bj[j].x;
                float v1 = d[i][j][half * 2 + 1] + bj[j].y;
                if (MODE == 0) {
                    v0 = 0.5f * v0 * (1.0f + erff(v0 * 0.70710678118654752f));
                    v1 = 0.5f * v1 * (1.0f + erff(v1 * 0.70710678118654752f));
                    float* dst = g_h + ((size_t)e * TTOK + m) * IDIM + n0 + cl;
                    *(float2*)dst = make_float2(v0, v1);
                } else if (MODE == 1) {
                    int tok = s_list[r];
                    float* dst = g_eo + (size_t)tok * HDIM + n0 + cl;
                    atomicAdd(dst + 0, v0);
                    atomicAdd(dst + 1, v1);
                } else {
                    float* dst = Out + (size_t)m * VDIM + n0 + cl;
                    *(float2*)dst = make_float2(v0, v1);
                }
            }
        }
    }
}

// ======================= launcher =======================
extern "C" void kernel_launch(void* const* d_in, const int* in_sizes, int n_in,
                              void* d_out, int out_size) {
    const int*   ids = (const int*)d_in[0];
    const float* emb = (const float*)d_in[1];
    const float* rw  = (const float*)d_in[2];
    const float* rb  = (const float*)d_in[3];
    const float* w1  = (const float*)d_in[4];
    const float* b1  = (const float*)d_in[5];
    const float* w2  = (const float*)d_in[6];
    const float* b2  = (const float*)d_in[7];
    const float* lw  = (const float*)d_in[8];
    const float* lb  = (const float*)d_in[9];

    float* out = (float*)d_out;
    const size_t LOG = (size_t)TTOK * VDIM;
    float* out_rw = nullptr;
    float* out_se = nullptr;
    if ((size_t)out_size >= LOG + (size_t)2 * TTOK * KTOP) {
        out_rw = out + LOG;
        out_se = out + LOG + (size_t)TTOK * KTOP;
    }

    static bool attr_done = false;
    if (!attr_done) {
        cudaFuncSetAttribute(gemm_mma<0>, cudaFuncAttributeMaxDynamicSharedMemorySize, SMEMSZ);
        cudaFuncSetAttribute(gemm_mma<1>, cudaFuncAttributeMaxDynamicSharedMemorySize, SMEMSZ);
        cudaFuncSetAttribute(gemm_mma<2>, cudaFuncAttributeMaxDynamicSharedMemorySize, SMEMSZ);
        attr_done = true;
    }

    setup_kernel<<<TTOK, 128>>>(ids, emb, rw, rb, out_rw, out_se);
    build_lists_kernel<<<ENUM, 256>>>();
    zero_eo_kernel<<<(TTOK * HDIM / 4 + 255) / 256, 256>>>();
    gemm_mma<0><<<dim3(IDIM / 256, TTOK / 128, ENUM), 256, SMEMSZ>>>(w1, b1, nullptr, HDIM, IDIM);
    gemm_mma<1><<<dim3(HDIM / 256, TTOK / 128, ENUM), 256, SMEMSZ>>>(w2, b2, nullptr, IDIM, HDIM);
    gemm_mma<2><<<dim3(VDIM / 256, TTOK / 128, 1), 256, SMEMSZ>>>(lw, lb, out, HDIM, VDIM);
}

// round 8
// speedup vs baseline: 1.0340x; 1.0340x over previous
#include <cuda_runtime.h>
#include <math.h>
#include <stdint.h>

#define TTOK 2048
#define HDIM 1024
#define ENUM 8
#define IDIM 4096
#define VDIM 32000
#define KTOP 2
#define KC   32

// ---- static scratch (no allocation allowed) ----
__device__ float g_x[(size_t)TTOK * HDIM];
__device__ float g_h[(size_t)ENUM * TTOK * IDIM];
__device__ float g_eo[(size_t)TTOK * HDIM];
__device__ int   g_sel[TTOK * KTOP];
__device__ int   g_list[ENUM][TTOK];
__device__ int   g_cnt[ENUM];

// ======================= helpers =======================
__device__ __forceinline__ uint32_t smem_u32(const void* p) {
    uint32_t a;
    asm("{ .reg .u64 t; cvta.to.shared.u64 t, %1; cvt.u32.u64 %0, t; }" : "=r"(a) : "l"(p));
    return a;
}
__device__ __forceinline__ uint32_t lds32(uint32_t a) {
    uint32_t v;
    asm volatile("ld.shared.b32 %0, [%1];" : "=r"(v) : "r"(a));
    return v;
}
__device__ __forceinline__ uint32_t cvt_rna(uint32_t x) {
    uint32_t v;
    asm("cvt.rna.tf32.f32 %0, %1;" : "=r"(v) : "r"(x));
    return v;
}
#define CP16Z(dst, src, sz) \
    asm volatile("cp.async.cg.shared.global [%0], [%1], 16, %2;" \
                 :: "r"(dst), "l"(src), "r"(sz))
#define CPCOMMIT() asm volatile("cp.async.commit_group;")
#define CPWAIT(n)  asm volatile("cp.async.wait_group %0;" :: "n"(n))

#define MMA_TF32(d, a, b)                                                      \
    asm volatile(                                                              \
        "mma.sync.aligned.m16n8k8.row.col.f32.tf32.tf32.f32 "                  \
        "{%0,%1,%2,%3},{%4,%5,%6,%7},{%8,%9},{%0,%1,%2,%3};"                   \
        : "+f"((d)[0]), "+f"((d)[1]), "+f"((d)[2]), "+f"((d)[3])               \
        : "r"((a)[0]), "r"((a)[1]), "r"((a)[2]), "r"((a)[3]),                  \
          "r"((b)[0]), "r"((b)[1]))

// ======================= small kernels =======================
__global__ void setup_kernel(const int* __restrict__ ids,
                             const float* __restrict__ emb,
                             const float* __restrict__ rw,
                             const float* __restrict__ rb,
                             float* __restrict__ out_rw,
                             float* __restrict__ out_se) {
    int t = blockIdx.x;
    int tid = threadIdx.x;
    int row = ids[t];
    const float* src = emb + (size_t)row * HDIM;
    const float4* s4 = (const float4*)src;
    float4* d4 = (float4*)(g_x + (size_t)t * HDIM);
    for (int i = tid; i < HDIM / 4; i += blockDim.x) d4[i] = s4[i];

    float acc[ENUM];
#pragma unroll
    for (int e = 0; e < ENUM; e++) acc[e] = 0.f;
    for (int k = tid; k < HDIM; k += blockDim.x) {
        float xv = src[k];
        const float* wr = rw + (size_t)k * ENUM;
#pragma unroll
        for (int e = 0; e < ENUM; e++) acc[e] = fmaf(xv, wr[e], acc[e]);
    }
    __shared__ float sred[ENUM][128];
#pragma unroll
    for (int e = 0; e < ENUM; e++) sred[e][tid] = acc[e];
    __syncthreads();
    for (int s = 64; s > 0; s >>= 1) {
        if (tid < s) {
#pragma unroll
            for (int e = 0; e < ENUM; e++) sred[e][tid] += sred[e][tid + s];
        }
        __syncthreads();
    }
    if (tid == 0) {
        float lg[ENUM];
#pragma unroll
        for (int e = 0; e < ENUM; e++) lg[e] = sred[e][0] + rb[e];
        int i0 = 0; float v0 = lg[0];
#pragma unroll
        for (int e = 1; e < ENUM; e++) if (lg[e] > v0) { v0 = lg[e]; i0 = e; }
        int i1 = -1; float v1 = -3.0e38f;
#pragma unroll
        for (int e = 0; e < ENUM; e++) if (e != i0 && lg[e] > v1) { v1 = lg[e]; i1 = e; }
        float ee = expf(v1 - v0);
        float denom = 1.0f + ee;
        g_sel[t * 2 + 0] = i0;
        g_sel[t * 2 + 1] = i1;
        if (out_rw) { out_rw[t * 2 + 0] = 1.0f / denom; out_rw[t * 2 + 1] = ee / denom; }
        if (out_se) { out_se[t * 2 + 0] = (float)i0; out_se[t * 2 + 1] = (float)i1; }
    }
}

__global__ void build_lists_kernel() {
    int e = blockIdx.x;
    int tid = threadIdx.x;
    int lane = tid & 31, wid = tid >> 5;
    __shared__ int wtot[8];
    __shared__ int s_base;
    if (tid == 0) s_base = 0;
    __syncthreads();
    for (int base = 0; base < TTOK; base += 256) {
        int t = base + tid;
        int f = (g_sel[t * 2] == e || g_sel[t * 2 + 1] == e) ? 1 : 0;
        unsigned bal = __ballot_sync(0xffffffffu, f);
        int lpfx = __popc(bal & ((1u << lane) - 1u));
        if (lane == 0) wtot[wid] = __popc(bal);
        __syncthreads();
        int woff = 0;
        for (int w = 0; w < wid; w++) woff += wtot[w];
        if (f) g_list[e][s_base + woff + lpfx] = t;
        int tot = 0;
        for (int w = 0; w < 8; w++) tot += wtot[w];
        __syncthreads();
        if (tid == 0) s_base += tot;
        __syncthreads();
    }
    if (tid == 0) g_cnt[e] = s_base;
}

__global__ void zero_eo_kernel() {
    size_t i = (size_t)blockIdx.x * blockDim.x + threadIdx.x;
    if (i < (size_t)TTOK * HDIM / 4) {
        ((float4*)g_eo)[i] = make_float4(0.f, 0.f, 0.f, 0.f);
    }
}

// ======================= tf32 mma.sync GEMM, 128x128 CTA, 3-stage pipeline =======================
// MODE 0: FFN1  gelu(Xg[e] @ w1[e] + b1[e]) -> g_h
// MODE 1: FFN2  (H[e] @ w2[e] + b2[e]) atomic-> g_eo
// MODE 2: LM    g_eo @ lm_w + lm_b -> out
//
// grid.x = M tiles (fast axis -> all M tiles of one N column concurrent -> B reused in L2)

#define SA 36                      // A smem row stride in floats (m-major)
#define SB 136                     // B smem row stride in floats (k-major)
#define AS_BYTES (128 * SA * 4)    // 18432
#define BS_BYTES (32 * SB * 4)     // 17408
#define NSTG 3
#define BSOFF (NSTG * AS_BYTES)           // 55296
#define LISTOFF (BSOFF + NSTG * BS_BYTES) // 107520
#define SMEMSZ (LISTOFF + 512)            // 108032

template <int MODE>
__global__ void __launch_bounds__(256) gemm_mma(
    const float* __restrict__ Bglob,
    const float* __restrict__ bias,
    float* __restrict__ Out,
    int Ktot, int ldb)
{
    int e = blockIdx.z;
    int cnt = (MODE == 2) ? TTOK : g_cnt[e];
    int m0 = blockIdx.x * 128;
    int n0 = blockIdx.y * 128;
    if (m0 >= cnt) return;

    extern __shared__ char smem[];
    int* s_list = (int*)(smem + LISTOFF);
    uint32_t sbase = smem_u32(smem);

    int tid = threadIdx.x;
    int lane = tid & 31;
    int wid = tid >> 5;
    int wm = wid >> 2;       // 0..1  (m)
    int wn = wid & 3;        // 0..3  (n)

    const float* Bg;
    const float* be;
    if (MODE == 0)      { Bg = Bglob + (size_t)e * HDIM * IDIM; be = bias + (size_t)e * IDIM; }
    else if (MODE == 1) { Bg = Bglob + (size_t)e * IDIM * HDIM; be = bias + (size_t)e * HDIM; }
    else                { Bg = Bglob; be = bias; }

    if (MODE != 2 && tid < 128) {
        int gm = m0 + tid;
        s_list[tid] = (gm < cnt) ? g_list[e][gm] : -1;
    }
    __syncthreads();

    // ---- cp.async source/dest assignments ----
    // A: 128 rows x 8 chunks(16B): row = (tid>>3)+32*i, chunk col = tid&7
    // B: 32 rows x 32 chunks(16B): row = (tid>>5)+8*i,  chunk col = tid&31
    int ac = tid & 7;
    int cb = tid & 31;
    const float* arow[4];
    uint32_t apred[4];
    uint32_t adst[4], bdst[4];
    int kb[4];
#pragma unroll
    for (int i = 0; i < 4; i++) {
        int r = (tid >> 3) + 32 * i;
        if (MODE == 0) {
            int tok = s_list[r];
            arow[i] = (tok >= 0) ? g_x + (size_t)tok * HDIM + ac * 4 : g_x;
            apred[i] = (tok >= 0) ? 16u : 0u;
        } else if (MODE == 1) {
            int gm = m0 + r;
            bool v = gm < cnt;
            arow[i] = v ? g_h + ((size_t)e * TTOK + gm) * IDIM + ac * 4 : g_h;
            apred[i] = v ? 16u : 0u;
        } else {
            arow[i] = g_eo + (size_t)(m0 + r) * HDIM + ac * 4;
            apred[i] = 16u;
        }
        adst[i] = sbase + (uint32_t)(r * SA * 4 + ac * 16);
        kb[i] = (tid >> 5) + 8 * i;
        bdst[i] = sbase + BSOFF + (uint32_t)(kb[i] * SB * 4 + cb * 16);
    }
    const float* bbase_g = Bg + n0 + cb * 4;

    float d[4][4][4];
#pragma unroll
    for (int i = 0; i < 4; i++)
#pragma unroll
        for (int j = 0; j < 4; j++)
#pragma unroll
            for (int r = 0; r < 4; r++) d[i][j][r] = 0.f;

    int nit = Ktot / KC;

    // ---- prologue: prefetch tiles 0 and 1 ----
#pragma unroll
    for (int i = 0; i < 4; i++) CP16Z(adst[i], arow[i], apred[i]);
#pragma unroll
    for (int i = 0; i < 4; i++) CP16Z(bdst[i], bbase_g + (size_t)kb[i] * ldb, 16u);
    CPCOMMIT();
    if (nit > 1) {
        uint32_t ao = AS_BYTES, bo = BS_BYTES;
#pragma unroll
        for (int i = 0; i < 4; i++) CP16Z(adst[i] + ao, arow[i] + KC, apred[i]);
#pragma unroll
        for (int i = 0; i < 4; i++)
            CP16Z(bdst[i] + bo, bbase_g + (size_t)(KC + kb[i]) * ldb, 16u);
    }
    CPCOMMIT();

    int ar_base = wm * 64 + (lane >> 2);
    int akc = lane & 3;
    int bnc = wn * 32 + (lane >> 2);

    int buf = 0;
    for (int it = 0; it < nit; ++it) {
        if (it + 1 < nit) { CPWAIT(1); } else { CPWAIT(0); }
        __syncthreads();

        // prefetch tile it+2 into buffer (it+2)%3 (freed: computed at it-1)
        if (it + 2 < nit) {
            int nb = buf + 2; if (nb >= NSTG) nb -= NSTG;
            int k0 = (it + 2) * KC;
            uint32_t ao = (uint32_t)(nb * AS_BYTES);
            uint32_t bo = (uint32_t)(nb * BS_BYTES);
#pragma unroll
            for (int i = 0; i < 4; i++) CP16Z(adst[i] + ao, arow[i] + k0, apred[i]);
#pragma unroll
            for (int i = 0; i < 4; i++)
                CP16Z(bdst[i] + bo, bbase_g + (size_t)(k0 + kb[i]) * ldb, 16u);
        }
        CPCOMMIT();

        uint32_t abase = sbase + (uint32_t)(buf * AS_BYTES);
        uint32_t bbase = sbase + BSOFF + (uint32_t)(buf * BS_BYTES);
#pragma unroll
        for (int ks = 0; ks < 4; ks++) {
            int c0 = ks * 8 + akc;
            uint32_t a[4][4];
#pragma unroll
            for (int i = 0; i < 4; i++) {
                int r0 = ar_base + i * 16;
                a[i][0] = cvt_rna(lds32(abase + (uint32_t)((r0 * SA + c0) * 4)));
                a[i][1] = cvt_rna(lds32(abase + (uint32_t)(((r0 + 8) * SA + c0) * 4)));
                a[i][2] = cvt_rna(lds32(abase + (uint32_t)((r0 * SA + c0 + 4) * 4)));
                a[i][3] = cvt_rna(lds32(abase + (uint32_t)(((r0 + 8) * SA + c0 + 4) * 4)));
            }
            uint32_t b[4][2];
#pragma unroll
            for (int j = 0; j < 4; j++) {
                b[j][0] = cvt_rna(lds32(bbase + (uint32_t)((c0 * SB + bnc + j * 8) * 4)));
                b[j][1] = cvt_rna(lds32(bbase + (uint32_t)(((c0 + 4) * SB + bnc + j * 8) * 4)));
            }
#pragma unroll
            for (int i = 0; i < 4; i++)
#pragma unroll
                for (int j = 0; j < 4; j++) MMA_TF32(d[i][j], a[i], b[j]);
        }
        if (++buf >= NSTG) buf = 0;
    }

    // ---- epilogue ----
    int row_l0 = wm * 64 + (lane >> 2);
    int col_l0 = wn * 32 + (lane & 3) * 2;
    float2 bj[4];
#pragma unroll
    for (int j = 0; j < 4; j++) {
        bj[j].x = be[n0 + col_l0 + j * 8];
        bj[j].y = be[n0 + col_l0 + j * 8 + 1];
    }

#pragma unroll
    for (int i = 0; i < 4; i++) {
        int rl = row_l0 + i * 16;
#pragma unroll
        for (int half = 0; half < 2; half++) {
            int r = rl + half * 8;
            int m = m0 + r;
            if (MODE != 2 && m >= cnt) continue;
#pragma unroll
            for (int j = 0; j < 4; j++) {
                int cl = col_l0 + j * 8;
                float v0 = d[i][j][half * 2 + 0] + bj[j].x;
                float v1 = d[i][j][half * 2 + 1] + bj[j].y;
                if (MODE == 0) {
                    v0 = 0.5f * v0 * (1.0f + erff(v0 * 0.70710678118654752f));
                    v1 = 0.5f * v1 * (1.0f + erff(v1 * 0.70710678118654752f));
                    float* dst = g_h + ((size_t)e * TTOK + m) * IDIM + n0 + cl;
                    *(float2*)dst = make_float2(v0, v1);
                } else if (MODE == 1) {
                    int tok = s_list[r];
                    float* dst = g_eo + (size_t)tok * HDIM + n0 + cl;
                    atomicAdd(dst + 0, v0);
                    atomicAdd(dst + 1, v1);
                } else {
                    float* dst = Out + (size_t)m * VDIM + n0 + cl;
                    *(float2*)dst = make_float2(v0, v1);
                }
            }
        }
    }
}

// ======================= launcher =======================
extern "C" void kernel_launch(void* const* d_in, const int* in_sizes, int n_in,
                              void* d_out, int out_size) {
    const int*   ids = (const int*)d_in[0];
    const float* emb = (const float*)d_in[1];
    const float* rw  = (const float*)d_in[2];
    const float* rb  = (const float*)d_in[3];
    const float* w1  = (const float*)d_in[4];
    const float* b1  = (const float*)d_in[5];
    const float* w2  = (const float*)d_in[6];
    const float* b2  = (const float*)d_in[7];
    const float* lw  = (const float*)d_in[8];
    const float* lb  = (const float*)d_in[9];

    float* out = (float*)d_out;
    const size_t LOG = (size_t)TTOK * VDIM;
    float* out_rw = nullptr;
    float* out_se = nullptr;
    if ((size_t)out_size >= LOG + (size_t)2 * TTOK * KTOP) {
        out_rw = out + LOG;
        out_se = out + LOG + (size_t)TTOK * KTOP;
    }

    static bool attr_done = false;
    if (!attr_done) {
        cudaFuncSetAttribute(gemm_mma<0>, cudaFuncAttributeMaxDynamicSharedMemorySize, SMEMSZ);
        cudaFuncSetAttribute(gemm_mma<1>, cudaFuncAttributeMaxDynamicSharedMemorySize, SMEMSZ);
        cudaFuncSetAttribute(gemm_mma<2>, cudaFuncAttributeMaxDynamicSharedMemorySize, SMEMSZ);
        attr_done = true;
    }

    setup_kernel<<<TTOK, 128>>>(ids, emb, rw, rb, out_rw, out_se);
    build_lists_kernel<<<ENUM, 256>>>();
    zero_eo_kernel<<<(TTOK * HDIM / 4 + 255) / 256, 256>>>();
    // grid.x = M tiles (fast) so concurrent CTAs share the same B tile via L2
    gemm_mma<0><<<dim3(TTOK / 128, IDIM / 128, ENUM), 256, SMEMSZ>>>(w1, b1, nullptr, HDIM, IDIM);
    gemm_mma<1><<<dim3(TTOK / 128, HDIM / 128, ENUM), 256, SMEMSZ>>>(w2, b2, nullptr, IDIM, HDIM);
    gemm_mma<2><<<dim3(TTOK / 128, VDIM / 128, 1), 256, SMEMSZ>>>(lw, lb, out, HDIM, VDIM);
}

// round 12
// speedup vs baseline: 1.1477x; 1.1100x over previous
#include <cuda_runtime.h>
#include <math.h>
#include <stdint.h>

#define TTOK 2048
#define HDIM 1024
#define ENUM 8
#define IDIM 4096
#define VDIM 32000
#define KTOP 2
#define KC   32

// ---- static scratch (no allocation allowed) ----
__device__ float g_x[(size_t)TTOK * HDIM];               // tf32-rounded activations
__device__ float g_h[(size_t)ENUM * TTOK * IDIM];        // tf32-rounded expert hidden
__device__ float g_eo[(size_t)TTOK * HDIM];              // rounded by round_eo pass
__device__ int   g_sel[TTOK * KTOP];
__device__ int   g_list[ENUM][TTOK];
__device__ int   g_cnt[ENUM];

// ======================= helpers =======================
__device__ __forceinline__ uint32_t smem_u32(const void* p) {
    uint32_t a;
    asm("{ .reg .u64 t; cvta.to.shared.u64 t, %1; cvt.u32.u64 %0, t; }" : "=r"(a) : "l"(p));
    return a;
}
__device__ __forceinline__ uint32_t lds32(uint32_t a) {
    uint32_t v;
    asm volatile("ld.shared.b32 %0, [%1];" : "=r"(v) : "r"(a));
    return v;
}
__device__ __forceinline__ uint32_t cvt_rna(uint32_t x) {
    uint32_t v;
    asm("cvt.rna.tf32.f32 %0, %1;" : "=r"(v) : "r"(x));
    return v;
}
__device__ __forceinline__ float round_tf32(float x) {
    return __uint_as_float(cvt_rna(__float_as_uint(x)));
}
#define CP16Z(dst, src, sz) \
    asm volatile("cp.async.cg.shared.global [%0], [%1], 16, %2;" \
                 :: "r"(dst), "l"(src), "r"(sz))
#define CPCOMMIT() asm volatile("cp.async.commit_group;")
#define CPWAIT(n)  asm volatile("cp.async.wait_group %0;" :: "n"(n))

// one ldmatrix.x4 delivers the full tf32 A-fragment (a0..a3) of one 16-row block
#define LDMX4(r, addr)                                                         \
    asm volatile("ldmatrix.sync.aligned.m8n8.x4.shared.b16 {%0,%1,%2,%3}, [%4];" \
        : "=r"((r)[0]), "=r"((r)[1]), "=r"((r)[2]), "=r"((r)[3]) : "r"(addr))

#define MMA_TF32(d, a, b)                                                      \
    asm volatile(                                                              \
        "mma.sync.aligned.m16n8k8.row.col.f32.tf32.tf32.f32 "                  \
        "{%0,%1,%2,%3},{%4,%5,%6,%7},{%8,%9},{%0,%1,%2,%3};"                   \
        : "+f"((d)[0]), "+f"((d)[1]), "+f"((d)[2]), "+f"((d)[3])               \
        : "r"((a)[0]), "r"((a)[1]), "r"((a)[2]), "r"((a)[3]),                  \
          "r"((b)[0]), "r"((b)[1]))

// ======================= small kernels =======================
__global__ void setup_kernel(const int* __restrict__ ids,
                             const float* __restrict__ emb,
                             const float* __restrict__ rw,
                             const float* __restrict__ rb,
                             float* __restrict__ out_rw,
                             float* __restrict__ out_se) {
    int t = blockIdx.x;
    int tid = threadIdx.x;
    int row = ids[t];
    const float* src = emb + (size_t)row * HDIM;
    const float4* s4 = (const float4*)src;
    float4* d4 = (float4*)(g_x + (size_t)t * HDIM);
    for (int i = tid; i < HDIM / 4; i += blockDim.x) {
        float4 v = s4[i];
        v.x = round_tf32(v.x); v.y = round_tf32(v.y);
        v.z = round_tf32(v.z); v.w = round_tf32(v.w);
        d4[i] = v;
    }

    float acc[ENUM];
#pragma unroll
    for (int e = 0; e < ENUM; e++) acc[e] = 0.f;
    for (int k = tid; k < HDIM; k += blockDim.x) {
        float xv = src[k];
        const float* wr = rw + (size_t)k * ENUM;
#pragma unroll
        for (int e = 0; e < ENUM; e++) acc[e] = fmaf(xv, wr[e], acc[e]);
    }
    __shared__ float sred[ENUM][128];
#pragma unroll
    for (int e = 0; e < ENUM; e++) sred[e][tid] = acc[e];
    __syncthreads();
    for (int s = 64; s > 0; s >>= 1) {
        if (tid < s) {
#pragma unroll
            for (int e = 0; e < ENUM; e++) sred[e][tid] += sred[e][tid + s];
        }
        __syncthreads();
    }
    if (tid == 0) {
        float lg[ENUM];
#pragma unroll
        for (int e = 0; e < ENUM; e++) lg[e] = sred[e][0] + rb[e];
        int i0 = 0; float v0 = lg[0];
#pragma unroll
        for (int e = 1; e < ENUM; e++) if (lg[e] > v0) { v0 = lg[e]; i0 = e; }
        int i1 = -1; float v1 = -3.0e38f;
#pragma unroll
        for (int e = 0; e < ENUM; e++) if (e != i0 && lg[e] > v1) { v1 = lg[e]; i1 = e; }
        float ee = expf(v1 - v0);
        float denom = 1.0f + ee;
        g_sel[t * 2 + 0] = i0;
        g_sel[t * 2 + 1] = i1;
        if (out_rw) { out_rw[t * 2 + 0] = 1.0f / denom; out_rw[t * 2 + 1] = ee / denom; }
        if (out_se) { out_se[t * 2 + 0] = (float)i0; out_se[t * 2 + 1] = (float)i1; }
    }
}

__global__ void build_lists_kernel() {
    int e = blockIdx.x;
    int tid = threadIdx.x;
    int lane = tid & 31, wid = tid >> 5;
    __shared__ int wtot[8];
    __shared__ int s_base;
    if (tid == 0) s_base = 0;
    __syncthreads();
    for (int base = 0; base < TTOK; base += 256) {
        int t = base + tid;
        int f = (g_sel[t * 2] == e || g_sel[t * 2 + 1] == e) ? 1 : 0;
        unsigned bal = __ballot_sync(0xffffffffu, f);
        int lpfx = __popc(bal & ((1u << lane) - 1u));
        if (lane == 0) wtot[wid] = __popc(bal);
        __syncthreads();
        int woff = 0;
        for (int w = 0; w < wid; w++) woff += wtot[w];
        if (f) g_list[e][s_base + woff + lpfx] = t;
        int tot = 0;
        for (int w = 0; w < 8; w++) tot += wtot[w];
        __syncthreads();
        if (tid == 0) s_base += tot;
        __syncthreads();
    }
    if (tid == 0) g_cnt[e] = s_base;
}

__global__ void zero_eo_kernel() {
    size_t i = (size_t)blockIdx.x * blockDim.x + threadIdx.x;
    if (i < (size_t)TTOK * HDIM / 4) {
        ((float4*)g_eo)[i] = make_float4(0.f, 0.f, 0.f, 0.f);
    }
}

// round g_eo to tf32 in place (so LM-head A side needs no consumer cvt)
__global__ void round_eo_kernel() {
    size_t i = (size_t)blockIdx.x * blockDim.x + threadIdx.x;
    if (i < (size_t)TTOK * HDIM / 4) {
        float4 v = ((float4*)g_eo)[i];
        v.x = round_tf32(v.x); v.y = round_tf32(v.y);
        v.z = round_tf32(v.z); v.w = round_tf32(v.w);
        ((float4*)g_eo)[i] = v;
    }
}

// ======================= tf32 mma.sync GEMM, ldmatrix A path =======================
// MODE 0: FFN1  gelu(Xg[e] @ w1[e] + b1[e]) -> g_h   (output rounded to tf32)
// MODE 1: FFN2  (H[e] @ w2[e] + b2[e]) atomic-> g_eo
// MODE 2: LM    g_eo @ lm_w + lm_b -> out
// grid.x = M tiles (fast) -> concurrent CTAs share B tiles in L2.

#define SA 36                      // A smem row stride in floats
#define SB 136                     // B smem row stride in floats
#define AS_BYTES (128 * SA * 4)    // 18432
#define BS_BYTES (32 * SB * 4)     // 17408
#define BSOFF (2 * AS_BYTES)       // 36864
#define LISTOFF (BSOFF + 2 * BS_BYTES)  // 71680
#define SMEMSZ (LISTOFF + 512)          // 72192

template <int MODE>
__global__ void __launch_bounds__(256) gemm_mma(
    const float* __restrict__ Bglob,
    const float* __restrict__ bias,
    float* __restrict__ Out,
    int Ktot, int ldb)
{
    int e = blockIdx.z;
    int cnt = (MODE == 2) ? TTOK : g_cnt[e];
    int m0 = blockIdx.x * 128;
    int n0 = blockIdx.y * 128;
    if (m0 >= cnt) return;

    extern __shared__ char smem[];
    int* s_list = (int*)(smem + LISTOFF);
    uint32_t sbase = smem_u32(smem);

    int tid = threadIdx.x;
    int lane = tid & 31;
    int wid = tid >> 5;
    int wm = wid >> 2;       // 0..1  (m)
    int wn = wid & 3;        // 0..3  (n)

    const float* Bg;
    const float* be;
    if (MODE == 0)      { Bg = Bglob + (size_t)e * HDIM * IDIM; be = bias + (size_t)e * IDIM; }
    else if (MODE == 1) { Bg = Bglob + (size_t)e * IDIM * HDIM; be = bias + (size_t)e * HDIM; }
    else                { Bg = Bglob; be = bias; }

    if (MODE != 2 && tid < 128) {
        int gm = m0 + tid;
        s_list[tid] = (gm < cnt) ? g_list[e][gm] : -1;
    }
    __syncthreads();

    // ---- cp.async source/dest assignments ----
    int ac = tid & 7;
    int cb = tid & 31;
    const float* arow[4];
    uint32_t apred[4];
    uint32_t adst[4], bdst[4];
    int kb[4];
#pragma unroll
    for (int i = 0; i < 4; i++) {
        int r = (tid >> 3) + 32 * i;
        if (MODE == 0) {
            int tok = s_list[r];
            arow[i] = (tok >= 0) ? g_x + (size_t)tok * HDIM + ac * 4 : g_x;
            apred[i] = (tok >= 0) ? 16u : 0u;
        } else if (MODE == 1) {
            int gm = m0 + r;
            bool v = gm < cnt;
            arow[i] = v ? g_h + ((size_t)e * TTOK + gm) * IDIM + ac * 4 : g_h;
            apred[i] = v ? 16u : 0u;
        } else {
            arow[i] = g_eo + (size_t)(m0 + r) * HDIM + ac * 4;
            apred[i] = 16u;
        }
        adst[i] = sbase + (uint32_t)(r * SA * 4 + ac * 16);
        kb[i] = (tid >> 5) + 8 * i;
        bdst[i] = sbase + BSOFF + (uint32_t)(kb[i] * SB * 4 + cb * 16);
    }
    const float* bbase_g = Bg + n0 + cb * 4;

    float d[4][4][4];
#pragma unroll
    for (int i = 0; i < 4; i++)
#pragma unroll
        for (int j = 0; j < 4; j++)
#pragma unroll
            for (int r = 0; r < 4; r++) d[i][j][r] = 0.f;

    int nit = Ktot / KC;

    // prefetch tile 0 into buffer 0
#pragma unroll
    for (int i = 0; i < 4; i++) CP16Z(adst[i], arow[i], apred[i]);
#pragma unroll
    for (int i = 0; i < 4; i++) CP16Z(bdst[i], bbase_g + (size_t)kb[i] * ldb, 16u);
    CPCOMMIT();

    // ldmatrix per-lane address pieces:
    //   mat = lane>>3 (0..3): mat0=a0 rows r..r+7 cols c..c+3; mat1=a1 rows +8;
    //   mat2=a2 cols +4; mat3=a3 rows +8 cols +4
    int mat = lane >> 3;
    int rl8 = lane & 7;
    uint32_t a_lane_off =
        (uint32_t)(((wm * 64 + (mat & 1) * 8 + rl8) * SA) * 4 + (mat >> 1) * 16);
    int bnc = wn * 32 + (lane >> 2);
    int akc = lane & 3;

    for (int it = 0; it < nit; ++it) {
        int buf = it & 1;
        if (it + 1 < nit) {
            int nbuf = (it + 1) & 1;
            int k0 = (it + 1) * KC;
            uint32_t ao = (uint32_t)(nbuf * AS_BYTES);
            uint32_t bo = (uint32_t)(nbuf * BS_BYTES);
#pragma unroll
            for (int i = 0; i < 4; i++) CP16Z(adst[i] + ao, arow[i] + k0, apred[i]);
#pragma unroll
            for (int i = 0; i < 4; i++)
                CP16Z(bdst[i] + bo, bbase_g + (size_t)(k0 + kb[i]) * ldb, 16u);
            CPCOMMIT();
            CPWAIT(1);
        } else {
            CPWAIT(0);
        }
        __syncthreads();

        uint32_t abase = sbase + (uint32_t)(buf * AS_BYTES) + a_lane_off;
        uint32_t bbase = sbase + BSOFF + (uint32_t)(buf * BS_BYTES);
#pragma unroll
        for (int ks = 0; ks < 4; ks++) {
            uint32_t a[4][4];
#pragma unroll
            for (int i = 0; i < 4; i++)
                LDMX4(a[i], abase + (uint32_t)(i * 16 * SA * 4 + ks * 32));
            int c0 = ks * 8 + akc;
            uint32_t b[4][2];
#pragma unroll
            for (int j = 0; j < 4; j++) {
                b[j][0] = cvt_rna(lds32(bbase + (uint32_t)((c0 * SB + bnc + j * 8) * 4)));
                b[j][1] = cvt_rna(lds32(bbase + (uint32_t)(((c0 + 4) * SB + bnc + j * 8) * 4)));
            }
#pragma unroll
            for (int i = 0; i < 4; i++)
#pragma unroll
                for (int j = 0; j < 4; j++) MMA_TF32(d[i][j], a[i], b[j]);
        }
        __syncthreads();
    }

    // ---- epilogue ----
    int row_l0 = wm * 64 + (lane >> 2);
    int col_l0 = wn * 32 + (lane & 3) * 2;
    float2 bj[4];
#pragma unroll
    for (int j = 0; j < 4; j++) {
        bj[j].x = be[n0 + col_l0 + j * 8];
        bj[j].y = be[n0 + col_l0 + j * 8 + 1];
    }

#pragma unroll
    for (int i = 0; i < 4; i++) {
        int rl = row_l0 + i * 16;
#pragma unroll
        for (int half = 0; half < 2; half++) {
            int r = rl + half * 8;
            int m = m0 + r;
            if (MODE != 2 && m >= cnt) continue;
#pragma unroll
            for (int j = 0; j < 4; j++) {
                int cl = col_l0 + j * 8;
                float v0 = d[i][j][half * 2 + 0] + bj[j].x;
                float v1 = d[i][j][half * 2 + 1] + bj[j].y;
                if (MODE == 0) {
                    v0 = 0.5f * v0 * (1.0f + erff(v0 * 0.70710678118654752f));
                    v1 = 0.5f * v1 * (1.0f + erff(v1 * 0.70710678118654752f));
                    v0 = round_tf32(v0);   // pre-round for ffn2's A side
                    v1 = round_tf32(v1);
                    float* dst = g_h + ((size_t)e * TTOK + m) * IDIM + n0 + cl;
                    *(float2*)dst = make_float2(v0, v1);
                } else if (MODE == 1) {
                    int tok = s_list[r];
                    float* dst = g_eo + (size_t)tok * HDIM + n0 + cl;
                    atomicAdd(dst + 0, v0);
                    atomicAdd(dst + 1, v1);
                } else {
                    float* dst = Out + (size_t)m * VDIM + n0 + cl;
                    *(float2*)dst = make_float2(v0, v1);
                }
            }
        }
    }
}

// ======================= launcher =======================
extern "C" void kernel_launch(void* const* d_in, const int* in_sizes, int n_in,
                              void* d_out, int out_size) {
    const int*   ids = (const int*)d_in[0];
    const float* emb = (const float*)d_in[1];
    const float* rw  = (const float*)d_in[2];
    const float* rb  = (const float*)d_in[3];
    const float* w1  = (const float*)d_in[4];
    const float* b1  = (const float*)d_in[5];
    const float* w2  = (const float*)d_in[6];
    const float* b2  = (const float*)d_in[7];
    const float* lw  = (const float*)d_in[8];
    const float* lb  = (const float*)d_in[9];

    float* out = (float*)d_out;
    const size_t LOG = (size_t)TTOK * VDIM;
    float* out_rw = nullptr;
    float* out_se = nullptr;
    if ((size_t)out_size >= LOG + (size_t)2 * TTOK * KTOP) {
        out_rw = out + LOG;
        out_se = out + LOG + (size_t)TTOK * KTOP;
    }

    static bool attr_done = false;
    if (!attr_done) {
        cudaFuncSetAttribute(gemm_mma<0>, cudaFuncAttributeMaxDynamicSharedMemorySize, SMEMSZ);
        cudaFuncSetAttribute(gemm_mma<1>, cudaFuncAttributeMaxDynamicSharedMemorySize, SMEMSZ);
        cudaFuncSetAttribute(gemm_mma<2>, cudaFuncAttributeMaxDynamicSharedMemorySize, SMEMSZ);
        attr_done = true;
    }

    setup_kernel<<<TTOK, 128>>>(ids, emb, rw, rb, out_rw, out_se);
    build_lists_kernel<<<ENUM, 256>>>();
    zero_eo_kernel<<<(TTOK * HDIM / 4 + 255) / 256, 256>>>();
    // grid.x = M tiles (fast) so concurrent CTAs share the same B tile via L2
    gemm_mma<0><<<dim3(TTOK / 128, IDIM / 128, ENUM), 256, SMEMSZ>>>(w1, b1, nullptr, HDIM, IDIM);
    gemm_mma<1><<<dim3(TTOK / 128, HDIM / 128, ENUM), 256, SMEMSZ>>>(w2, b2, nullptr, IDIM, HDIM);
    round_eo_kernel<<<(TTOK * HDIM / 4 + 255) / 256, 256>>>();
    gemm_mma<2><<<dim3(TTOK / 128, VDIM / 128, 1), 256, SMEMSZ>>>(lw, lb, out, HDIM, VDIM);
}

// round 13
// speedup vs baseline: 1.8039x; 1.5718x over previous
#include <cuda_runtime.h>
#include <cuda_fp16.h>
#include <math.h>
#include <stdint.h>

#define TTOK 2048
#define HDIM 1024
#define ENUM 8
#define IDIM 4096
#define VDIM 32000
#define KTOP 2
#define KC   32

// ---- static scratch (no allocation allowed) ----
__device__ __half g_xh[(size_t)TTOK * HDIM];              // fp16 activations
__device__ __half g_hh[(size_t)ENUM * TTOK * IDIM];       // fp16 expert hidden
__device__ float  g_eo[(size_t)TTOK * HDIM];              // fp32 atomic combine
__device__ __half g_eoh[(size_t)TTOK * HDIM];             // fp16 copy for LM head
__device__ int    g_sel[TTOK * KTOP];
__device__ int    g_list[ENUM][TTOK];
__device__ int    g_cnt[ENUM];

// ======================= helpers =======================
__device__ __forceinline__ uint32_t smem_u32(const void* p) {
    uint32_t a;
    asm("{ .reg .u64 t; cvta.to.shared.u64 t, %1; cvt.u32.u64 %0, t; }" : "=r"(a) : "l"(p));
    return a;
}
__device__ __forceinline__ float ldsf(uint32_t a) {
    float v;
    asm volatile("ld.shared.f32 %0, [%1];" : "=f"(v) : "r"(a));
    return v;
}
// pack two fp32 -> fp16x2 (lo = second operand)
__device__ __forceinline__ uint32_t f2h2(float hi, float lo) {
    uint32_t r;
    asm("cvt.rn.f16x2.f32 %0, %1, %2;" : "=r"(r) : "f"(hi), "f"(lo));
    return r;
}
#define CP16Z(dst, src, sz) \
    asm volatile("cp.async.cg.shared.global [%0], [%1], 16, %2;" \
                 :: "r"(dst), "l"(src), "r"(sz))
#define CPCOMMIT() asm volatile("cp.async.commit_group;")
#define CPWAIT(n)  asm volatile("cp.async.wait_group %0;" :: "n"(n))

#define LDMX4(r, addr)                                                         \
    asm volatile("ldmatrix.sync.aligned.m8n8.x4.shared.b16 {%0,%1,%2,%3}, [%4];" \
        : "=r"((r)[0]), "=r"((r)[1]), "=r"((r)[2]), "=r"((r)[3]) : "r"(addr))

#define MMA_F16(d, a, b)                                                       \
    asm volatile(                                                              \
        "mma.sync.aligned.m16n8k16.row.col.f32.f16.f16.f32 "                   \
        "{%0,%1,%2,%3},{%4,%5,%6,%7},{%8,%9},{%0,%1,%2,%3};"                   \
        : "+f"((d)[0]), "+f"((d)[1]), "+f"((d)[2]), "+f"((d)[3])               \
        : "r"((a)[0]), "r"((a)[1]), "r"((a)[2]), "r"((a)[3]),                  \
          "r"((b)[0]), "r"((b)[1]))

// ======================= small kernels =======================
__global__ void setup_kernel(const int* __restrict__ ids,
                             const float* __restrict__ emb,
                             const float* __restrict__ rw,
                             const float* __restrict__ rb,
                             float* __restrict__ out_rw,
                             float* __restrict__ out_se) {
    int t = blockIdx.x;
    int tid = threadIdx.x;
    int row = ids[t];
    const float* src = emb + (size_t)row * HDIM;
    const float4* s4 = (const float4*)src;
    uint2* dh = (uint2*)(g_xh + (size_t)t * HDIM);
    for (int i = tid; i < HDIM / 4; i += blockDim.x) {
        float4 v = s4[i];
        uint2 h;
        h.x = f2h2(v.y, v.x);
        h.y = f2h2(v.w, v.z);
        dh[i] = h;
    }

    float acc[ENUM];
#pragma unroll
    for (int e = 0; e < ENUM; e++) acc[e] = 0.f;
    for (int k = tid; k < HDIM; k += blockDim.x) {
        float xv = src[k];
        const float* wr = rw + (size_t)k * ENUM;
#pragma unroll
        for (int e = 0; e < ENUM; e++) acc[e] = fmaf(xv, wr[e], acc[e]);
    }
    __shared__ float sred[ENUM][128];
#pragma unroll
    for (int e = 0; e < ENUM; e++) sred[e][tid] = acc[e];
    __syncthreads();
    for (int s = 64; s > 0; s >>= 1) {
        if (tid < s) {
#pragma unroll
            for (int e = 0; e < ENUM; e++) sred[e][tid] += sred[e][tid + s];
        }
        __syncthreads();
    }
    if (tid == 0) {
        float lg[ENUM];
#pragma unroll
        for (int e = 0; e < ENUM; e++) lg[e] = sred[e][0] + rb[e];
        int i0 = 0; float v0 = lg[0];
#pragma unroll
        for (int e = 1; e < ENUM; e++) if (lg[e] > v0) { v0 = lg[e]; i0 = e; }
        int i1 = -1; float v1 = -3.0e38f;
#pragma unroll
        for (int e = 0; e < ENUM; e++) if (e != i0 && lg[e] > v1) { v1 = lg[e]; i1 = e; }
        float ee = expf(v1 - v0);
        float denom = 1.0f + ee;
        g_sel[t * 2 + 0] = i0;
        g_sel[t * 2 + 1] = i1;
        if (out_rw) { out_rw[t * 2 + 0] = 1.0f / denom; out_rw[t * 2 + 1] = ee / denom; }
        if (out_se) { out_se[t * 2 + 0] = (float)i0; out_se[t * 2 + 1] = (float)i1; }
    }
}

__global__ void build_lists_kernel() {
    int e = blockIdx.x;
    int tid = threadIdx.x;
    int lane = tid & 31, wid = tid >> 5;
    __shared__ int wtot[8];
    __shared__ int s_base;
    if (tid == 0) s_base = 0;
    __syncthreads();
    for (int base = 0; base < TTOK; base += 256) {
        int t = base + tid;
        int f = (g_sel[t * 2] == e || g_sel[t * 2 + 1] == e) ? 1 : 0;
        unsigned bal = __ballot_sync(0xffffffffu, f);
        int lpfx = __popc(bal & ((1u << lane) - 1u));
        if (lane == 0) wtot[wid] = __popc(bal);
        __syncthreads();
        int woff = 0;
        for (int w = 0; w < wid; w++) woff += wtot[w];
        if (f) g_list[e][s_base + woff + lpfx] = t;
        int tot = 0;
        for (int w = 0; w < 8; w++) tot += wtot[w];
        __syncthreads();
        if (tid == 0) s_base += tot;
        __syncthreads();
    }
    if (tid == 0) g_cnt[e] = s_base;
}

__global__ void zero_eo_kernel() {
    size_t i = (size_t)blockIdx.x * blockDim.x + threadIdx.x;
    if (i < (size_t)TTOK * HDIM / 4) {
        ((float4*)g_eo)[i] = make_float4(0.f, 0.f, 0.f, 0.f);
    }
}

// g_eo (fp32) -> g_eoh (fp16) for LM-head A side
__global__ void cvt_eo_kernel() {
    size_t i = (size_t)blockIdx.x * blockDim.x + threadIdx.x;
    if (i < (size_t)TTOK * HDIM / 4) {
        float4 v = ((float4*)g_eo)[i];
        uint2 h;
        h.x = f2h2(v.y, v.x);
        h.y = f2h2(v.w, v.z);
        ((uint2*)g_eoh)[i] = h;
    }
}

// ======================= fp16 mma.sync GEMM =======================
// MODE 0: FFN1  gelu(Xg[e] @ w1[e] + b1[e]) -> g_hh (fp16)
// MODE 1: FFN2  (H[e] @ w2[e] + b2[e]) atomic-> g_eo (fp32)
// MODE 2: LM    g_eoh @ lm_w + lm_b -> out
// A: fp16 smem (80B rows, ldmatrix.b16). B: fp32 smem, XOR-chunk swizzle,
// cvt.rn.f16x2 at fragment build. grid.x = M tiles for L2 weight reuse.

#define SAH 80                      // A smem row stride in BYTES (40 halves)
#define ABUF (128 * SAH)            // 10240
#define BS_BYTES (32 * 512)         // 16384 (32 k-rows x 128 floats, swizzled)
#define BSOFF (2 * ABUF)            // 20480
#define LISTOFF (BSOFF + 2 * BS_BYTES)  // 53248
#define SMEMSZ (LISTOFF + 512)          // 53760

template <int MODE>
__global__ void __launch_bounds__(256) gemm_mma(
    const float* __restrict__ Bglob,
    const float* __restrict__ bias,
    float* __restrict__ Out,
    int Ktot, int ldb)
{
    int e = blockIdx.z;
    int cnt = (MODE == 2) ? TTOK : g_cnt[e];
    int m0 = blockIdx.x * 128;
    int n0 = blockIdx.y * 128;
    if (m0 >= cnt) return;

    extern __shared__ char smem[];
    int* s_list = (int*)(smem + LISTOFF);
    uint32_t sbase = smem_u32(smem);

    int tid = threadIdx.x;
    int lane = tid & 31;
    int wid = tid >> 5;
    int wm = wid >> 2;       // 0..1  (m)
    int wn = wid & 3;        // 0..3  (n)

    const float* Bg;
    const float* be;
    if (MODE == 0)      { Bg = Bglob + (size_t)e * HDIM * IDIM; be = bias + (size_t)e * IDIM; }
    else if (MODE == 1) { Bg = Bglob + (size_t)e * IDIM * HDIM; be = bias + (size_t)e * HDIM; }
    else                { Bg = Bglob; be = bias; }

    if (MODE != 2 && tid < 128) {
        int gm = m0 + tid;
        s_list[tid] = (gm < cnt) ? g_list[e][gm] : -1;
    }
    __syncthreads();

    // ---- A cp.async: row = tid>>1, two 16B chunks (8 halves each) ----
    int arow_i = tid >> 1;
    int ac4 = (tid & 1) * 2;          // first chunk index (of 4 per row)
    const __half* asrc;
    uint32_t apred;
    if (MODE == 0) {
        int tok = s_list[arow_i];
        asrc = (tok >= 0) ? g_xh + (size_t)tok * HDIM + ac4 * 8 : g_xh;
        apred = (tok >= 0) ? 16u : 0u;
    } else if (MODE == 1) {
        bool v = (m0 + arow_i) < cnt;
        asrc = v ? g_hh + ((size_t)e * TTOK + m0 + arow_i) * IDIM + ac4 * 8 : g_hh;
        apred = v ? 16u : 0u;
    } else {
        asrc = g_eoh + (size_t)(m0 + arow_i) * HDIM + ac4 * 8;
        apred = 16u;
    }
    uint32_t adst = sbase + (uint32_t)(arow_i * SAH + ac4 * 16);

    // ---- B cp.async: 32 k-rows x 32 chunks, XOR swizzle chunk^(k&7) ----
    int cb = tid & 31;
    int kb[4];
    uint32_t bdst[4];
#pragma unroll
    for (int i = 0; i < 4; i++) {
        kb[i] = (tid >> 5) + 8 * i;
        int cbs = cb ^ (kb[i] & 7);
        bdst[i] = sbase + BSOFF + (uint32_t)(kb[i] * 512 + cbs * 16);
    }
    const float* bbase_g = Bg + n0 + cb * 4;

    float d[4][4][4];
#pragma unroll
    for (int i = 0; i < 4; i++)
#pragma unroll
        for (int j = 0; j < 4; j++)
#pragma unroll
            for (int r = 0; r < 4; r++) d[i][j][r] = 0.f;

    int nit = Ktot / KC;

    // prefetch tile 0
    CP16Z(adst, asrc, apred);
    CP16Z(adst + 16, asrc + 8, apred);
#pragma unroll
    for (int i = 0; i < 4; i++) CP16Z(bdst[i], bbase_g + (size_t)kb[i] * ldb, 16u);
    CPCOMMIT();

    // ldmatrix lane address: mat = lane>>3 (0:r+0/k0, 1:r+8/k0, 2:r+0/k8, 3:r+8/k8)
    int mat = lane >> 3;
    int rl8 = lane & 7;
    uint32_t a_lane_off =
        (uint32_t)((wm * 64 + (mat & 1) * 8 + rl8) * SAH + (mat >> 1) * 16);
    // B fragment n-index
    int nidx0 = wn * 32 + (lane >> 2);

    for (int it = 0; it < nit; ++it) {
        int buf = it & 1;
        if (it + 1 < nit) {
            int nbuf = (it + 1) & 1;
            int k0 = (it + 1) * KC;
            uint32_t ao = (uint32_t)(nbuf * ABUF);
            uint32_t bo = (uint32_t)(nbuf * BS_BYTES);
            CP16Z(adst + ao, asrc + k0, apred);
            CP16Z(adst + ao + 16, asrc + k0 + 8, apred);
#pragma unroll
            for (int i = 0; i < 4; i++)
                CP16Z(bdst[i] + bo, bbase_g + (size_t)(k0 + kb[i]) * ldb, 16u);
            CPCOMMIT();
            CPWAIT(1);
        } else {
            CPWAIT(0);
        }
        __syncthreads();

        uint32_t abase = sbase + (uint32_t)(buf * ABUF) + a_lane_off;
        uint32_t bbase = sbase + BSOFF + (uint32_t)(buf * BS_BYTES);
#pragma unroll
        for (int ks = 0; ks < 2; ks++) {
            uint32_t a[4][4];
#pragma unroll
            for (int i = 0; i < 4; i++)
                LDMX4(a[i], abase + (uint32_t)(i * 16 * SAH + ks * 32));
            int c0 = ks * 16 + (lane & 3) * 2;
            uint32_t b[4][2];
#pragma unroll
            for (int j = 0; j < 4; j++) {
                int n = nidx0 + j * 8;
                int n4 = n >> 2;
                uint32_t nb4 = (uint32_t)((n & 3) * 4);
                int ca = c0, cb2 = c0 + 1, cc = c0 + 8, cd = c0 + 9;
                float f00 = ldsf(bbase + (uint32_t)(ca * 512) + (uint32_t)(((n4 ^ (ca & 7)) << 4)) + nb4);
                float f01 = ldsf(bbase + (uint32_t)(cb2 * 512) + (uint32_t)(((n4 ^ (cb2 & 7)) << 4)) + nb4);
                float f10 = ldsf(bbase + (uint32_t)(cc * 512) + (uint32_t)(((n4 ^ (cc & 7)) << 4)) + nb4);
                float f11 = ldsf(bbase + (uint32_t)(cd * 512) + (uint32_t)(((n4 ^ (cd & 7)) << 4)) + nb4);
                b[j][0] = f2h2(f01, f00);
                b[j][1] = f2h2(f11, f10);
            }
#pragma unroll
            for (int i = 0; i < 4; i++)
#pragma unroll
                for (int j = 0; j < 4; j++) MMA_F16(d[i][j], a[i], b[j]);
        }
        __syncthreads();
    }

    // ---- epilogue ----
    int row_l0 = wm * 64 + (lane >> 2);
    int col_l0 = wn * 32 + (lane & 3) * 2;
    float2 bj[4];
#pragma unroll
    for (int j = 0; j < 4; j++) {
        bj[j].x = be[n0 + col_l0 + j * 8];
        bj[j].y = be[n0 + col_l0 + j * 8 + 1];
    }

#pragma unroll
    for (int i = 0; i < 4; i++) {
        int rl = row_l0 + i * 16;
#pragma unroll
        for (int half = 0; half < 2; half++) {
            int r = rl + half * 8;
            int m = m0 + r;
            if (MODE != 2 && m >= cnt) continue;
#pragma unroll
            for (int j = 0; j < 4; j++) {
                int cl = col_l0 + j * 8;
                float v0 = d[i][j][half * 2 + 0] + bj[j].x;
                float v1 = d[i][j][half * 2 + 1] + bj[j].y;
                if (MODE == 0) {
                    v0 = 0.5f * v0 * (1.0f + erff(v0 * 0.70710678118654752f));
                    v1 = 0.5f * v1 * (1.0f + erff(v1 * 0.70710678118654752f));
                    uint32_t* dst = (uint32_t*)(g_hh + ((size_t)e * TTOK + m) * IDIM + n0 + cl);
                    *dst = f2h2(v1, v0);
                } else if (MODE == 1) {
                    int tok = s_list[r];
                    float* dst = g_eo + (size_t)tok * HDIM + n0 + cl;
                    atomicAdd(dst + 0, v0);
                    atomicAdd(dst + 1, v1);
                } else {
                    float* dst = Out + (size_t)m * VDIM + n0 + cl;
                    *(float2*)dst = make_float2(v0, v1);
                }
            }
        }
    }
}

// ======================= launcher =======================
extern "C" void kernel_launch(void* const* d_in, const int* in_sizes, int n_in,
                              void* d_out, int out_size) {
    const int*   ids = (const int*)d_in[0];
    const float* emb = (const float*)d_in[1];
    const float* rw  = (const float*)d_in[2];
    const float* rb  = (const float*)d_in[3];
    const float* w1  = (const float*)d_in[4];
    const float* b1  = (const float*)d_in[5];
    const float* w2  = (const float*)d_in[6];
    const float* b2  = (const float*)d_in[7];
    const float* lw  = (const float*)d_in[8];
    const float* lb  = (const float*)d_in[9];

    float* out = (float*)d_out;
    const size_t LOG = (size_t)TTOK * VDIM;
    float* out_rw = nullptr;
    float* out_se = nullptr;
    if ((size_t)out_size >= LOG + (size_t)2 * TTOK * KTOP) {
        out_rw = out + LOG;
        out_se = out + LOG + (size_t)TTOK * KTOP;
    }

    static bool attr_done = false;
    if (!attr_done) {
        cudaFuncSetAttribute(gemm_mma<0>, cudaFuncAttributeMaxDynamicSharedMemorySize, SMEMSZ);
        cudaFuncSetAttribute(gemm_mma<1>, cudaFuncAttributeMaxDynamicSharedMemorySize, SMEMSZ);
        cudaFuncSetAttribute(gemm_mma<2>, cudaFuncAttributeMaxDynamicSharedMemorySize, SMEMSZ);
        attr_done = true;
    }

    setup_kernel<<<TTOK, 128>>>(ids, emb, rw, rb, out_rw, out_se);
    build_lists_kernel<<<ENUM, 256>>>();
    zero_eo_kernel<<<(TTOK * HDIM / 4 + 255) / 256, 256>>>();
    gemm_mma<0><<<dim3(TTOK / 128, IDIM / 128, ENUM), 256, SMEMSZ>>>(w1, b1, nullptr, HDIM, IDIM);
    gemm_mma<1><<<dim3(TTOK / 128, HDIM / 128, ENUM), 256, SMEMSZ>>>(w2, b2, nullptr, IDIM, HDIM);
    cvt_eo_kernel<<<(TTOK * HDIM / 4 + 255) / 256, 256>>>();
    gemm_mma<2><<<dim3(TTOK / 128, VDIM / 128, 1), 256, SMEMSZ>>>(lw, lb, out, HDIM, VDIM);
}